// round 14
// baseline (speedup 1.0000x reference)
#include <cuda_runtime.h>
#include <math.h>
#include <stdint.h>

// Problem constants
#define S_TOK 65536
#define H_DIM 768
#define T_TYP 6
#define K_TOP 3
#define WIN   15

// ---------------------------------------------------------------------------
// Device scratch (no allocations allowed in kernel_launch)
// ---------------------------------------------------------------------------
__device__ float g_start[T_TYP * S_TOK];   // column-major [t][s]
__device__ float g_end  [T_TYP * S_TOK];   // column-major [t][s]
__device__ float g_pooled[H_DIM];          // atomic-accumulated column sums of X
__device__ float g_m[T_TYP];               // per-column max of start scores
__device__ float g_s[T_TYP];               // per-column sum exp(x - m)
__device__ float g_topv[T_TYP * K_TOP];    // top-3 raw start scores (desc)
__device__ int   g_topi[T_TYP * K_TOP];    // their indices

// ---------------------------------------------------------------------------
// Kernel 0: zero the pooled accumulator (required every graph replay)
// ---------------------------------------------------------------------------
__global__ void zero_pool_kernel() {
    int i = blockIdx.x * blockDim.x + threadIdx.x;
    if (i < H_DIM) g_pooled[i] = 0.0f;
}

// ---------------------------------------------------------------------------
// Helpers
// ---------------------------------------------------------------------------
__device__ __forceinline__ float4 wsum4(float4 v) {
#pragma unroll
    for (int off = 16; off > 0; off >>= 1) {
        v.x += __shfl_xor_sync(0xffffffffu, v.x, off);
        v.y += __shfl_xor_sync(0xffffffffu, v.y, off);
        v.z += __shfl_xor_sync(0xffffffffu, v.z, off);
        v.w += __shfl_xor_sync(0xffffffffu, v.w, off);
    }
    return v;
}

// Inline function (NOT a macro: a macro parameter named `w` would get
// substituted into the `.w` member accessor by the preprocessor).
__device__ __forceinline__ void fma4(float4& acc, const float4 wv, const float xs) {
    acc.x = fmaf(wv.x, xs, acc.x);
    acc.y = fmaf(wv.y, xs, acc.y);
    acc.z = fmaf(wv.z, xs, acc.z);
    acc.w = fmaf(wv.w, xs, acc.w);
}

__device__ __forceinline__ float comp4(float4 v, int kk) {
    // kk is a compile-time constant at every call site (unrolled loops)
    return kk == 0 ? v.x : (kk == 1 ? v.y : (kk == 2 ? v.z : v.w));
}

// ---------------------------------------------------------------------------
// Kernel 1: fused GEMV x12 + column-sum of X.
// 1024 blocks x 256 threads. Each warp owns 8 contiguous rows (2 groups of 4).
// Lanes split H: lane covers h = i*128 + lane*4 .. +3 for chunk i in 0..5.
// W_start||W_end packed in smem as Wc[k][12] (48B/k -> conflict-free LDS.128).
// ---------------------------------------------------------------------------
__global__ void __launch_bounds__(256)
main_pass_kernel(const float* __restrict__ X,
                 const float* __restrict__ Ws,
                 const float* __restrict__ We) {
    __shared__ __align__(16) float swc[H_DIM * 12];
    __shared__ __align__(16) float sp[H_DIM];

    const int tid    = threadIdx.x;
    const int warpId = tid >> 5;
    const int lane   = tid & 31;

    // stage combined weights
    for (int i = tid; i < H_DIM * 12; i += 256) {
        int k = i / 12, c = i % 12;
        swc[i] = (c < 6) ? Ws[k * 6 + c] : We[k * 6 + (c - 6)];
    }
    __syncthreads();

    const int wg = blockIdx.x * 8 + warpId;   // 8192 warps total

    float4 pacc[6];
#pragma unroll
    for (int i = 0; i < 6; i++) pacc[i] = make_float4(0.f, 0.f, 0.f, 0.f);

#pragma unroll
    for (int grp = 0; grp < 2; grp++) {
        const int row0 = wg * 8 + grp * 4;
        const float* xp = X + (size_t)row0 * H_DIM + lane * 4;

        float4 a[4][3];
#pragma unroll
        for (int r = 0; r < 4; r++)
#pragma unroll
            for (int g = 0; g < 3; g++) a[r][g] = make_float4(0.f, 0.f, 0.f, 0.f);

#pragma unroll
        for (int i = 0; i < 6; i++) {
            float4 x0 = *(const float4*)(xp + 0 * H_DIM + i * 128);
            float4 x1 = *(const float4*)(xp + 1 * H_DIM + i * 128);
            float4 x2 = *(const float4*)(xp + 2 * H_DIM + i * 128);
            float4 x3 = *(const float4*)(xp + 3 * H_DIM + i * 128);

            pacc[i].x += x0.x + x1.x + x2.x + x3.x;
            pacc[i].y += x0.y + x1.y + x2.y + x3.y;
            pacc[i].z += x0.z + x1.z + x2.z + x3.z;
            pacc[i].w += x0.w + x1.w + x2.w + x3.w;

            const float* wb = swc + (size_t)(i * 128 + lane * 4) * 12;
#pragma unroll
            for (int kk = 0; kk < 4; kk++) {
                float4 w0 = *(const float4*)(wb + kk * 12 + 0);
                float4 w1 = *(const float4*)(wb + kk * 12 + 4);
                float4 w2 = *(const float4*)(wb + kk * 12 + 8);
                float xv0 = comp4(x0, kk);
                float xv1 = comp4(x1, kk);
                float xv2 = comp4(x2, kk);
                float xv3 = comp4(x3, kk);
                fma4(a[0][0], w0, xv0); fma4(a[0][1], w1, xv0); fma4(a[0][2], w2, xv0);
                fma4(a[1][0], w0, xv1); fma4(a[1][1], w1, xv1); fma4(a[1][2], w2, xv1);
                fma4(a[2][0], w0, xv2); fma4(a[2][1], w1, xv2); fma4(a[2][2], w2, xv2);
                fma4(a[3][0], w0, xv3); fma4(a[3][1], w1, xv3); fma4(a[3][2], w2, xv3);
            }
        }

        // reduce 12 scores per row across the warp, lane 0 stores
#pragma unroll
        for (int r = 0; r < 4; r++) {
            float4 s0 = wsum4(a[r][0]);
            float4 s1 = wsum4(a[r][1]);
            float4 s2 = wsum4(a[r][2]);
            if (lane == 0) {
                const int row = row0 + r;
                g_start[0 * S_TOK + row] = s0.x;
                g_start[1 * S_TOK + row] = s0.y;
                g_start[2 * S_TOK + row] = s0.z;
                g_start[3 * S_TOK + row] = s0.w;
                g_start[4 * S_TOK + row] = s1.x;
                g_start[5 * S_TOK + row] = s1.y;
                g_end  [0 * S_TOK + row] = s1.z;
                g_end  [1 * S_TOK + row] = s1.w;
                g_end  [2 * S_TOK + row] = s2.x;
                g_end  [3 * S_TOK + row] = s2.y;
                g_end  [4 * S_TOK + row] = s2.z;
                g_end  [5 * S_TOK + row] = s2.w;
            }
        }
    }

    // combine pooled partials across the 8 warps (serialized, no smem atomics)
    for (int w = 0; w < 8; w++) {
        if (warpId == w) {
#pragma unroll
            for (int i = 0; i < 6; i++) {
                float4* p = (float4*)&sp[i * 128 + lane * 4];
                if (w == 0) {
                    *p = pacc[i];
                } else {
                    float4 cur = *p;
                    cur.x += pacc[i].x; cur.y += pacc[i].y;
                    cur.z += pacc[i].z; cur.w += pacc[i].w;
                    *p = cur;
                }
            }
        }
        __syncthreads();
    }
    for (int h = tid; h < H_DIM; h += 256) atomicAdd(&g_pooled[h], sp[h]);
}

// ---------------------------------------------------------------------------
// Kernel 2: per-column online (max, sumexp) + top-3 of raw start scores.
// 6 blocks x 1024 threads, strided coalesced scan + smem tree merge.
// ---------------------------------------------------------------------------
__device__ __forceinline__ bool better(float av, int ai, float bv, int bi) {
    return (av > bv) || (av == bv && ai < bi);
}
__device__ __forceinline__ void insert3(float cv, int ci,
                                        float& v0, int& i0,
                                        float& v1, int& i1,
                                        float& v2, int& i2) {
    if (better(cv, ci, v0, i0)) {
        v2 = v1; i2 = i1; v1 = v0; i1 = i0; v0 = cv; i0 = ci;
    } else if (better(cv, ci, v1, i1)) {
        v2 = v1; i2 = i1; v1 = cv; i1 = ci;
    } else if (better(cv, ci, v2, i2)) {
        v2 = cv; i2 = ci;
    }
}

__global__ void __launch_bounds__(1024) stats_kernel() {
    __shared__ float smm[1024];
    __shared__ float sms[1024];
    __shared__ float smv[1024 * 3];
    __shared__ int   smi[1024 * 3];

    const int t   = blockIdx.x;
    const int tid = threadIdx.x;
    const float* __restrict__ col = g_start + (size_t)t * S_TOK;

    float m = -INFINITY, s = 0.0f;
    float v0 = -INFINITY, v1 = -INFINITY, v2 = -INFINITY;
    int   i0 = 0x7fffffff, i1 = 0x7fffffff, i2 = 0x7fffffff;

    for (int j = tid; j < S_TOK; j += 1024) {
        float v = col[j];
        if (v > m) { s = s * __expf(m - v) + 1.0f; m = v; }
        else       { s += __expf(v - m); }
        insert3(v, j, v0, i0, v1, i1, v2, i2);
    }

    smm[tid] = m; sms[tid] = s;
    smv[tid * 3 + 0] = v0; smi[tid * 3 + 0] = i0;
    smv[tid * 3 + 1] = v1; smi[tid * 3 + 1] = i1;
    smv[tid * 3 + 2] = v2; smi[tid * 3 + 2] = i2;
    __syncthreads();

    for (int stride = 512; stride >= 1; stride >>= 1) {
        if (tid < stride) {
            int o = tid + stride;
            float om = smm[o], os = sms[o];
            if (om > m) { s = s * __expf(m - om) + os; m = om; }
            else        { s = s + os * __expf(om - m); }
#pragma unroll
            for (int q = 0; q < 3; q++)
                insert3(smv[o * 3 + q], smi[o * 3 + q], v0, i0, v1, i1, v2, i2);
            smm[tid] = m; sms[tid] = s;
            smv[tid * 3 + 0] = v0; smi[tid * 3 + 0] = i0;
            smv[tid * 3 + 1] = v1; smi[tid * 3 + 1] = i1;
            smv[tid * 3 + 2] = v2; smi[tid * 3 + 2] = i2;
        }
        __syncthreads();
    }

    if (tid == 0) {
        g_m[t] = m; g_s[t] = s;
        g_topv[t * 3 + 0] = v0; g_topi[t * 3 + 0] = i0;
        g_topv[t * 3 + 1] = v1; g_topi[t * 3 + 1] = i1;
        g_topv[t * 3 + 2] = v2; g_topi[t * 3 + 2] = i2;
    }
}

// ---------------------------------------------------------------------------
// Kernel 3: pooled-mean MLP (exact GELU + sigmoid) + window argmax + outputs.
// Output layout: [conf(18) | starts(18) | ends(18) | valid(18)] as float32.
// ---------------------------------------------------------------------------
__global__ void __launch_bounds__(256)
final_kernel(const float* __restrict__ W1, const float* __restrict__ b1,
             const float* __restrict__ W2, const float* __restrict__ b2,
             float* __restrict__ out) {
    __shared__ float sp[H_DIM];
    __shared__ float spart[4][64];
    __shared__ float sh[64];
    __shared__ float stc[T_TYP];

    const int tid = threadIdx.x;

    for (int h = tid; h < H_DIM; h += 256)
        sp[h] = g_pooled[h] * (1.0f / (float)S_TOK);
    __syncthreads();

    {   // h = gelu(pooled @ W1 + b1), split K over 4 partitions
        int j = tid & 63, part = tid >> 6;
        float acc = 0.0f;
        int k0 = part * 192;
        for (int k = k0; k < k0 + 192; k++)
            acc = fmaf(sp[k], W1[k * 64 + j], acc);
        spart[part][j] = acc;
    }
    __syncthreads();

    if (tid < 64) {
        float z = spart[0][tid] + spart[1][tid] + spart[2][tid] + spart[3][tid] + b1[tid];
        sh[tid] = 0.5f * z * (1.0f + erff(z * 0.70710678118654752f));
    }
    __syncthreads();

    if (tid < T_TYP) {
        float z = b2[tid];
        for (int j = 0; j < 64; j++)
            z = fmaf(sh[j], W2[j * 6 + tid], z);
        stc[tid] = 1.0f / (1.0f + expf(-z));
    }
    __syncthreads();

    if (tid < T_TYP * K_TOP) {
        const int t = tid / K_TOP;
        const int idx = g_topi[tid];
        const float v = g_topv[tid];
        const float prob = __expf(v - g_m[t]) / g_s[t];   // softmax top value

        const float* __restrict__ ecol = g_end + (size_t)t * S_TOK;
        float best = -INFINITY;
        int   boff = 0;
#pragma unroll
        for (int j = 0; j < WIN; j++) {
            int p = idx + j;
            if (p < S_TOK) {
                float ev = ecol[p];
                if (ev > best) { best = ev; boff = j; }
            }
        }

        const float tc = stc[t];
        const bool valid = (tc >= 0.3f) && (prob >= 0.15f);
        out[tid]          = valid ? prob * tc : 0.0f;
        out[18 + tid]     = (float)idx;
        out[36 + tid]     = (float)(idx + boff + 1);
        out[54 + tid]     = valid ? 1.0f : 0.0f;
    }
}

// ---------------------------------------------------------------------------
// Launch. Inputs (metadata order):
// 0 token_embeds (S*H f32), 1 W_start (H*T), 2 b_start, 3 W_end (H*T),
// 4 b_end, 5 W1 (H*64), 6 b1 (64), 7 W2 (64*T), 8 b2 (T)
// Biases b_start/b_end are exactly irrelevant to the outputs (softmax &
// windowed-argmax are invariant to per-column shifts; the reference's bias
// arrays are zeros anyway), so the fused pass stores raw dot products.
// ---------------------------------------------------------------------------
extern "C" void kernel_launch(void* const* d_in, const int* in_sizes, int n_in,
                              void* d_out, int out_size) {
    const float* X  = (const float*)d_in[0];
    const float* Ws = (const float*)d_in[1];
    const float* We = (const float*)d_in[3];
    const float* W1 = (const float*)d_in[5];
    const float* b1 = (const float*)d_in[6];
    const float* W2 = (const float*)d_in[7];
    const float* b2 = (const float*)d_in[8];
    float* out = (float*)d_out;

    zero_pool_kernel<<<3, 256>>>();
    main_pass_kernel<<<1024, 256>>>(X, Ws, We);
    stats_kernel<<<T_TYP, 1024>>>();
    final_kernel<<<1, 256>>>(W1, b1, W2, b2, out);
}